// round 2
// baseline (speedup 1.0000x reference)
#include <cuda_runtime.h>

#define IN_DIM 768
#define OUT_DIM 768
#define BATCH 32
#define NUMF 8

#define O_TILE 128          // o's per block (32 o-groups x 4)
#define CHUNK 12            // i's per block
#define NCHUNK (IN_DIM / CHUNK)   // 64 i-chunks

// Precomputed basis: Ssin[(i*8+k)*32 + b] = sin(grid[k]*x2[b,i])
//                    Sbase[i*32 + b]      = silu(x2[b,i])
__device__ float g_Ssin[IN_DIM * NUMF * BATCH];
__device__ float g_Sbase[IN_DIM * BATCH];

// ---- f32x2 helpers (sm_103a packed fp32 FMA) ----
__device__ __forceinline__ unsigned long long pk2(float lo, float hi) {
    unsigned long long r;
    asm("mov.b64 %0, {%1, %2};" : "=l"(r) : "f"(lo), "f"(hi));
    return r;
}
__device__ __forceinline__ void upk2(unsigned long long v, float& lo, float& hi) {
    asm("mov.b64 {%0, %1}, %2;" : "=f"(lo), "=f"(hi) : "l"(v));
}
__device__ __forceinline__ void fma2(unsigned long long& d,
                                     unsigned long long a,
                                     unsigned long long b) {
    asm("fma.rn.f32x2 %0, %1, %2, %0;" : "+l"(d) : "l"(a), "l"(b));
}

// -------- Kernel P: basis precompute --------
__global__ void precompute_kernel(const float* __restrict__ x,
                                  const float* __restrict__ grid) {
    int t = blockIdx.x * blockDim.x + threadIdx.x;
    if (t >= IN_DIM * BATCH) return;
    int i = t >> 5;
    int b = t & 31;
    float xv = x[b * IN_DIM + i];
    // silu(x) = x * sigmoid(x)
    g_Sbase[i * BATCH + b] = xv / (1.0f + expf(-xv));
#pragma unroll
    for (int k = 0; k < NUMF; k++) {
        float g = __ldg(grid + k);
        g_Ssin[(i * NUMF + k) * BATCH + b] = sinf(g * xv);
    }
}

// -------- Kernel I: init output with bias --------
__global__ void init_kernel(const float* __restrict__ bias, float* __restrict__ y) {
    int t = blockIdx.x * blockDim.x + threadIdx.x;
    if (t < BATCH * OUT_DIM) y[t] = bias[t % OUT_DIM];
}

// -------- Kernel G: skinny GEMM, thread tile 4o x 8b, f32x2 packed --------
__global__ __launch_bounds__(128) void gemm_kernel(
    const float* __restrict__ coef,
    const float* __restrict__ scale_sp,
    const float* __restrict__ scale_base,
    float* __restrict__ y) {
    int tid = threadIdx.x;
    int bg = tid & 3;            // 4 batch-groups of 8 batches
    int og = tid >> 2;           // 32 o-groups of 4 outputs
    int o0 = blockIdx.x * O_TILE + og * 4;
    int b0 = bg * 8;
    int i0 = blockIdx.y * CHUNK;

    unsigned long long acc[4][4];   // [o][b-pair], each = f32x2 over (b, b+1)
#pragma unroll
    for (int j = 0; j < 4; j++)
#pragma unroll
        for (int p = 0; p < 4; p++) acc[j][p] = 0ULL;  // bits of {0.f,0.f}

    for (int ii = 0; ii < CHUNK; ii++) {
        int i = i0 + ii;

        // ---- load & scale weights for this thread's 4 outputs ----
        float w[4][8];
        float wb[4];
#pragma unroll
        for (int j = 0; j < 4; j++) {
            int idx = (o0 + j) * IN_DIM + i;          // < 589824, fits int32
            const float4* cp = reinterpret_cast<const float4*>(coef + (size_t)idx * 8);
            float4 c0 = cp[0];
            float4 c1 = cp[1];
            float sp = __ldg(scale_sp + idx);
            wb[j]    = __ldg(scale_base + idx);
            w[j][0] = c0.x * sp; w[j][1] = c0.y * sp;
            w[j][2] = c0.z * sp; w[j][3] = c0.w * sp;
            w[j][4] = c1.x * sp; w[j][5] = c1.y * sp;
            w[j][6] = c1.z * sp; w[j][7] = c1.w * sp;
        }

        // ---- base (silu) term: s-pairs load pre-packed as doubles ----
        {
            const double2* s2p = reinterpret_cast<const double2*>(g_Sbase + i * BATCH + b0);
            double2 sa = s2p[0], sb = s2p[1];
            unsigned long long s[4] = {
                __double_as_longlong(sa.x), __double_as_longlong(sa.y),
                __double_as_longlong(sb.x), __double_as_longlong(sb.y)};
#pragma unroll
            for (int j = 0; j < 4; j++) {
                unsigned long long wd = pk2(wb[j], wb[j]);
#pragma unroll
                for (int p = 0; p < 4; p++) fma2(acc[j][p], wd, s[p]);
            }
        }

        // ---- 8 sin-basis terms ----
#pragma unroll
        for (int k = 0; k < NUMF; k++) {
            const double2* s2p =
                reinterpret_cast<const double2*>(g_Ssin + (i * NUMF + k) * BATCH + b0);
            double2 sa = s2p[0], sb = s2p[1];
            unsigned long long s[4] = {
                __double_as_longlong(sa.x), __double_as_longlong(sa.y),
                __double_as_longlong(sb.x), __double_as_longlong(sb.y)};
#pragma unroll
            for (int j = 0; j < 4; j++) {
                unsigned long long wd = pk2(w[j][k], w[j][k]);
#pragma unroll
                for (int p = 0; p < 4; p++) fma2(acc[j][p], wd, s[p]);
            }
        }
    }

    // ---- epilogue: partial-sum into y via atomics ----
#pragma unroll
    for (int j = 0; j < 4; j++) {
        int oc = o0 + j;
#pragma unroll
        for (int p = 0; p < 4; p++) {
            float lo, hi;
            upk2(acc[j][p], lo, hi);
            atomicAdd(&y[(b0 + 2 * p) * OUT_DIM + oc], lo);
            atomicAdd(&y[(b0 + 2 * p + 1) * OUT_DIM + oc], hi);
        }
    }
}

extern "C" void kernel_launch(void* const* d_in, const int* in_sizes, int n_in,
                              void* d_out, int out_size) {
    // metadata order = setup_inputs order: x, grid, coef, bias_w, scale_base, scale_sp
    const float* x          = (const float*)d_in[0];
    const float* grid       = (const float*)d_in[1];
    const float* coef       = (const float*)d_in[2];
    const float* bias_w     = (const float*)d_in[3];
    const float* scale_base = (const float*)d_in[4];
    const float* scale_sp   = (const float*)d_in[5];
    float* y = (float*)d_out;

    precompute_kernel<<<(IN_DIM * BATCH + 255) / 256, 256>>>(x, grid);
    init_kernel<<<(BATCH * OUT_DIM + 255) / 256, 256>>>(bias_w, y);
    dim3 g(OUT_DIM / O_TILE, NCHUNK);   // 6 x 64 = 384 blocks
    gemm_kernel<<<g, 128>>>(coef, scale_sp, scale_base, y);
}